// round 3
// baseline (speedup 1.0000x reference)
#include <cuda_runtime.h>
#include <math.h>

// Problem constants
#define NB    64
#define NPOMO 200
#define NPROB 200
#define NEMB  512
#define NHEAD 16
#define NHD   32
#define NNODE 201   // PROB + 1

// ---------------- scratch (device globals; no runtime allocation) -----------
static __device__ float g_kbuf[(size_t)NB * NNODE * NEMB];          // 26.3 MB
static __device__ float g_vbuf[(size_t)NB * NNODE * NEMB];          // 26.3 MB
static __device__ float g_qbuf[(size_t)NB * NPOMO * NEMB];          // 26.2 MB
static __device__ float g_sbuf[(size_t)NB * NHEAD * NPOMO * NNODE]; // 164.7 MB
static __device__ float g_obuf[(size_t)NB * NPOMO * NEMB];          // 26.2 MB
static __device__ float g_mhbuf[(size_t)NB * NPOMO * NEMB];         // 26.2 MB

// ---------------- generic batched GEMM ---------------------------------------
// C[z] = epilogue( alpha * (A[z] @ B[z]  (+ A2[z] @ B2[z])) )
// z = zb * nbH + zh; per-operand strides for zb and zh.
// transB: B is stored (N x K) row-major, we need B[k][n] = Bst[n][k].
// epMode: 0 none, 1 +bias[col], 2 10*tanh(v)+mask, 3 v+mask
#define BMT 64
#define BNT 128
#define BKT 16

__global__ __launch_bounds__(256)
void gemm_kernel(const float* __restrict__ A0, const float* __restrict__ B0,
                 const float* __restrict__ A1p, const float* __restrict__ B1p,
                 const float* __restrict__ bias, const float* __restrict__ mask,
                 float* __restrict__ C,
                 int M, int N, int K,
                 int lda, int ldb, int ldc,
                 long long aSb, long long aSh,
                 long long bSb, long long bSh,
                 long long cSb, long long cSh,
                 long long mSb,
                 int nbH, int transB, int epMode, int maskCols, float alpha)
{
    __shared__ float sA[BKT][BMT];
    __shared__ float sB[BKT][BNT];

    const int t  = threadIdx.x;
    const int zb = blockIdx.z / nbH;
    const int zh = blockIdx.z - zb * nbH;
    const int m0 = blockIdx.y * BMT;
    const int n0 = blockIdx.x * BNT;

    const long long aOff = (long long)zb * aSb + (long long)zh * aSh;
    const long long bOff = (long long)zb * bSb + (long long)zh * bSh;
    float* Cp = C + (long long)zb * cSb + (long long)zh * cSh;
    const float* Mp = mask ? (mask + (long long)zb * mSb) : nullptr;

    float acc[4][8];
#pragma unroll
    for (int i = 0; i < 4; i++)
#pragma unroll
        for (int j = 0; j < 8; j++) acc[i][j] = 0.0f;

    const int ty = t >> 4;   // 0..15 -> rows ty*4..+3
    const int tx = t & 15;   // 0..15 -> cols tx*8..+7

    const int nsrc = (A1p != nullptr) ? 2 : 1;

    for (int src = 0; src < nsrc; src++) {
        const float* Ap = (src ? A1p : A0) + aOff;
        const float* Bp = (src ? B1p : B0) + bOff;

        for (int k0 = 0; k0 < K; k0 += BKT) {
            // ---- load A tile (BM x BK), store k-major ----
            {
                const int mloc = t >> 2;
                const int kg   = (t & 3) * 4;
                const int row  = m0 + mloc;
#pragma unroll
                for (int j = 0; j < 4; j++) {
                    const int kk = k0 + kg + j;
                    float v = 0.0f;
                    if (row < M && kk < K) v = Ap[(long long)row * lda + kk];
                    sA[kg + j][mloc] = v;
                }
            }
            // ---- load B tile (BK x BN) ----
            if (!transB) {
                const int kloc = t >> 4;
                const int ng   = (t & 15) * 8;
                const int kk   = k0 + kloc;
#pragma unroll
                for (int j = 0; j < 8; j++) {
                    const int col = n0 + ng + j;
                    float v = 0.0f;
                    if (kk < K && col < N) v = Bp[(long long)kk * ldb + col];
                    sB[kloc][ng + j] = v;
                }
            } else {
                const int nloc = t >> 1;
                const int kg   = (t & 1) * 8;
                const int col  = n0 + nloc;
#pragma unroll
                for (int j = 0; j < 8; j++) {
                    const int kk = k0 + kg + j;
                    float v = 0.0f;
                    if (col < N && kk < K) v = Bp[(long long)col * ldb + kk];
                    sB[kg + j][nloc] = v;
                }
            }
            __syncthreads();

#pragma unroll
            for (int kk = 0; kk < BKT; kk++) {
                const float4 a4  = *(const float4*)&sA[kk][ty * 4];
                const float4 b4a = *(const float4*)&sB[kk][tx * 8];
                const float4 b4b = *(const float4*)&sB[kk][tx * 8 + 4];
                const float a[4] = {a4.x, a4.y, a4.z, a4.w};
                const float b[8] = {b4a.x, b4a.y, b4a.z, b4a.w,
                                    b4b.x, b4b.y, b4b.z, b4b.w};
#pragma unroll
                for (int i = 0; i < 4; i++)
#pragma unroll
                    for (int j = 0; j < 8; j++)
                        acc[i][j] = fmaf(a[i], b[j], acc[i][j]);
            }
            __syncthreads();
        }
    }

    // ---- epilogue ----
#pragma unroll
    for (int i = 0; i < 4; i++) {
        const int row = m0 + ty * 4 + i;
        if (row >= M) continue;
#pragma unroll
        for (int j = 0; j < 8; j++) {
            const int col = n0 + tx * 8 + j;
            if (col >= N) continue;
            float v = acc[i][j] * alpha;
            if (epMode == 1) {
                v += bias[col];
            } else if (epMode == 2) {
                v = 10.0f * tanhf(v);
                if (col < maskCols) v += Mp[(long long)row * maskCols + col];
            } else if (epMode == 3) {
                if (col < maskCols) v += Mp[(long long)row * maskCols + col];
            }
            Cp[(long long)row * ldc + col] = v;
        }
    }
}

// ---------------- row softmax (in place), warp per row ----------------------
__global__ __launch_bounds__(256)
void softmax_kernel(float* __restrict__ X, int rows, int L)
{
    const int gwarp = (blockIdx.x * blockDim.x + threadIdx.x) >> 5;
    const int lane  = threadIdx.x & 31;
    if (gwarp >= rows) return;
    float* rowp = X + (long long)gwarp * L;

    float vals[7];
    float mx = -INFINITY;
#pragma unroll
    for (int i = 0; i < 7; i++) {
        const int idx = lane + i * 32;
        const float v = (idx < L) ? rowp[idx] : -INFINITY;
        vals[i] = v;
        mx = fmaxf(mx, v);
    }
#pragma unroll
    for (int o = 16; o > 0; o >>= 1) mx = fmaxf(mx, __shfl_xor_sync(0xffffffffu, mx, o));

    float sum = 0.0f;
#pragma unroll
    for (int i = 0; i < 7; i++) {
        const int idx = lane + i * 32;
        const float e = (idx < L) ? expf(vals[i] - mx) : 0.0f;
        vals[i] = e;
        sum += e;
    }
#pragma unroll
    for (int o = 16; o > 0; o >>= 1) sum += __shfl_xor_sync(0xffffffffu, sum, o);

    const float inv = 1.0f / sum;
#pragma unroll
    for (int i = 0; i < 7; i++) {
        const int idx = lane + i * 32;
        if (idx < L) rowp[idx] = vals[i] * inv;
    }
}

// ---------------- launch ------------------------------------------------------
static inline int cdiv(int a, int b) { return (a + b - 1) / b; }

extern "C" void kernel_launch(void* const* d_in, const int* in_sizes, int n_in,
                              void* d_out, int out_size)
{
    const float* nodes = (const float*)d_in[0];  // (64, 201, 512)
    const float* q1    = (const float*)d_in[1];  // (64, 200, 512)
    const float* lastn = (const float*)d_in[2];  // (64, 200, 512)
    const float* ninf  = (const float*)d_in[3];  // (64, 200, 200)
    const float* Wqf   = (const float*)d_in[4];  // (512, 512)
    const float* Wql   = (const float*)d_in[5];
    const float* Wk    = (const float*)d_in[6];
    const float* Wv    = (const float*)d_in[7];
    const float* Wc    = (const float*)d_in[8];
    const float* bc    = (const float*)d_in[9];  // (512,)
    float* out = (float*)d_out;                  // (64, 200, 200)

    float *kbuf, *vbuf, *qbuf, *sbuf, *obuf, *mhbuf;
    cudaGetSymbolAddress((void**)&kbuf,  g_kbuf);
    cudaGetSymbolAddress((void**)&vbuf,  g_vbuf);
    cudaGetSymbolAddress((void**)&qbuf,  g_qbuf);
    cudaGetSymbolAddress((void**)&sbuf,  g_sbuf);
    cudaGetSymbolAddress((void**)&obuf,  g_obuf);
    cudaGetSymbolAddress((void**)&mhbuf, g_mhbuf);

    const dim3 blk(256);
    const float inv_sqrt_d   = 0.17677669529663687f;   // 1/sqrt(32)
    const float inv_sqrt_emb = 0.04419417382415922f;   // 1/22.627416997969522

    const int Mn = NB * NNODE;   // 12864
    const int Mq = NB * NPOMO;   // 12800

    // 1) K projection: kbuf = nodes @ Wk        (12864 x 512 x 512)
    gemm_kernel<<<dim3(cdiv(NEMB, BNT), cdiv(Mn, BMT), 1), blk>>>(
        nodes, Wk, nullptr, nullptr, nullptr, nullptr, kbuf,
        Mn, NEMB, NEMB, NEMB, NEMB, NEMB,
        0, 0, 0, 0, 0, 0, 0,
        1, 0, 0, 0, 1.0f);

    // 2) V projection
    gemm_kernel<<<dim3(cdiv(NEMB, BNT), cdiv(Mn, BMT), 1), blk>>>(
        nodes, Wv, nullptr, nullptr, nullptr, nullptr, vbuf,
        Mn, NEMB, NEMB, NEMB, NEMB, NEMB,
        0, 0, 0, 0, 0, 0, 0,
        1, 0, 0, 0, 1.0f);

    // 3) Q projection (fused dual GEMM): qbuf = q1@Wqf + lastn@Wql
    gemm_kernel<<<dim3(cdiv(NEMB, BNT), cdiv(Mq, BMT), 1), blk>>>(
        q1, Wqf, lastn, Wql, nullptr, nullptr, qbuf,
        Mq, NEMB, NEMB, NEMB, NEMB, NEMB,
        0, 0, 0, 0, 0, 0, 0,
        1, 0, 0, 0, 1.0f);

    // 4) attention scores per (b,h): S = Q @ K^T / sqrt(D) + mask3
    //    A = qbuf[b, :, h*32:(h+1)*32] (200 x 32, lda 512)
    //    B = kbuf[b, :, h*32:(h+1)*32] (201 x 32, transB)
    //    C = sbuf[(b*16+h)] (200 x 201)
    gemm_kernel<<<dim3(cdiv(NNODE, BNT), cdiv(NPOMO, BMT), NB * NHEAD), blk>>>(
        qbuf, kbuf, nullptr, nullptr, nullptr, ninf, sbuf,
        NPOMO, NNODE, NHD, NEMB, NEMB, NNODE,
        (long long)NPOMO * NEMB, NHD,
        (long long)NNODE * NEMB, NHD,
        (long long)NHEAD * NPOMO * NNODE, (long long)NPOMO * NNODE,
        (long long)NPOMO * NPROB,
        NHEAD, 1, 3, NPROB, inv_sqrt_d);

    // 5) softmax over m (201) for 64*16*200 rows
    {
        const int rows = NB * NHEAD * NPOMO;
        softmax_kernel<<<cdiv(rows, 8), blk>>>(sbuf, rows, NNODE);
    }

    // 6) O = S @ V per (b,h): (200 x 32, K=201), written interleaved into obuf
    gemm_kernel<<<dim3(cdiv(NHD, BNT), cdiv(NPOMO, BMT), NB * NHEAD), blk>>>(
        sbuf, vbuf, nullptr, nullptr, nullptr, nullptr, obuf,
        NPOMO, NHD, NNODE, NNODE, NEMB, NEMB,
        (long long)NHEAD * NPOMO * NNODE, (long long)NPOMO * NNODE,
        (long long)NNODE * NEMB, NHD,
        (long long)NPOMO * NEMB, NHD,
        0,
        NHEAD, 0, 0, 0, 1.0f);

    // 7) mh = obuf @ Wc + bc   (12800 x 512 x 512)
    gemm_kernel<<<dim3(cdiv(NEMB, BNT), cdiv(Mq, BMT), 1), blk>>>(
        obuf, Wc, nullptr, nullptr, bc, nullptr, mhbuf,
        Mq, NEMB, NEMB, NEMB, NEMB, NEMB,
        0, 0, 0, 0, 0, 0, 0,
        1, 0, 1, 0, 1.0f);

    // 8) score2 per b: out = 10*tanh(mh @ nodes[:,:200]^T / sqrt(EMB)) + ninf
    gemm_kernel<<<dim3(cdiv(NPROB, BNT), cdiv(NPOMO, BMT), NB), blk>>>(
        mhbuf, nodes, nullptr, nullptr, nullptr, ninf, out,
        NPOMO, NPROB, NEMB, NEMB, NEMB, NPROB,
        (long long)NPOMO * NEMB, 0,
        (long long)NNODE * NEMB, 0,
        (long long)NPOMO * NPROB, 0,
        (long long)NPOMO * NPROB,
        1, 1, 2, NPROB, inv_sqrt_emb);

    // 9) final softmax over p (200) for 64*200 rows, in place on out
    {
        const int rows = NB * NPOMO;
        softmax_kernel<<<cdiv(rows, 8), blk>>>(out, rows, NPROB);
    }
}

// round 6
// speedup vs baseline: 1.3325x; 1.3325x over previous
#include <cuda_runtime.h>
#include <math.h>
#include <stdint.h>

#define NB    64
#define NPOMO 200
#define NPROB 200
#define NEMB  512
#define NHEAD 16
#define NHD   32
#define NNODE 201
#define SLD   204   // padded score-row stride (float4-aligned)

// ---------------- scratch (device globals) -----------------------------------
static __device__ float g_kbuf[(size_t)NB * NNODE * NEMB];
static __device__ float g_vbuf[(size_t)NB * NNODE * NEMB];
static __device__ float g_qbuf[(size_t)NB * NPOMO * NEMB];
static __device__ float g_sbuf[(size_t)NB * NHEAD * NPOMO * SLD];
static __device__ float g_obuf[(size_t)NB * NPOMO * NEMB];
static __device__ float g_mhbuf[(size_t)NB * NPOMO * NEMB];

__device__ __forceinline__ uint32_t f2tf(float x) {
    uint32_t r;
    asm("cvt.rna.tf32.f32 %0, %1;" : "=r"(r) : "f"(x));
    return r;
}
// tf32 value for term: hi (rounded) or lo (rounded residual)
__device__ __forceinline__ uint32_t tfterm(float x, bool lo) {
    const uint32_t hi = f2tf(x);
    return lo ? f2tf(x - __uint_as_float(hi)) : hi;
}
__device__ __forceinline__ void mma8(float* c, const uint32_t* a, const uint32_t* b) {
    asm volatile(
        "mma.sync.aligned.m16n8k8.row.col.f32.tf32.tf32.f32 "
        "{%0,%1,%2,%3},{%4,%5,%6,%7},{%8,%9},{%0,%1,%2,%3};"
        : "+f"(c[0]), "+f"(c[1]), "+f"(c[2]), "+f"(c[3])
        : "r"(a[0]), "r"(a[1]), "r"(a[2]), "r"(a[3]), "r"(b[0]), "r"(b[1]));
}
__device__ __forceinline__ float4 ldg4(const float* p, bool ok, int rem) {
    float4 v = make_float4(0.f, 0.f, 0.f, 0.f);
    if (ok && rem > 0) {
        if (rem >= 4) v = *(const float4*)p;
        else { v.x = p[0]; if (rem > 1) v.y = p[1]; if (rem > 2) v.z = p[2]; }
    }
    return v;
}

// ---------------- TF32 tensor-core GEMM, 3-term compensated split ------------
// C[z]=epi(alpha*(A@op(B) (+A2@op(B2)))). BM=128, BK=16, 256 thr (2x4 warps).
// Every GEMM runs 3 passes over K: A_hi*B_hi + A_hi*B_lo + A_lo*B_hi  (~fp32).
// epMode: 0 none, 1 +bias, 2 10*tanh+mask, 3 +mask
template <int BN>
__global__ void __launch_bounds__(256)
tf32_gemm(const float* __restrict__ A0, const float* __restrict__ B0,
          const float* __restrict__ A1, const float* __restrict__ B1,
          const float* __restrict__ bias, const float* __restrict__ mask,
          float* __restrict__ C, int M, int N, int K,
          int lda, int ldb, int ldc,
          long long aSb, long long aSh, long long bSb, long long bSh,
          long long cSb, long long cSh, long long mSb,
          int nbH, int transB, int epMode, int maskCols, float alpha)
{
    constexpr int SAST = 133, SBST = BN + 5, NW = BN / 32, BF4 = 4 * BN;
    __shared__ uint32_t sA[2][16][SAST];
    __shared__ uint32_t sB[2][16][SBST];

    const int t = threadIdx.x, lane = t & 31, wid = t >> 5;
    const int wm = wid & 1, wn = wid >> 1, g = lane >> 2, c4 = lane & 3;
    const int zb = blockIdx.z / nbH, zh = blockIdx.z - zb * nbH;
    const int m0 = blockIdx.y * 128, n0 = blockIdx.x * BN;

    const long long aOff = (long long)zb * aSb + (long long)zh * aSh;
    const long long bOff = (long long)zb * bSb + (long long)zh * bSh;
    float* Cp = C + (long long)zb * cSb + (long long)zh * cSh;
    const float* Mp = mask ? (mask + (long long)zb * mSb) : nullptr;

    float acc[4][NW][4];
#pragma unroll
    for (int mi = 0; mi < 4; mi++)
#pragma unroll
        for (int ni = 0; ni < NW; ni++)
#pragma unroll
            for (int j = 0; j < 4; j++) acc[mi][ni][j] = 0.f;

    const int nkt  = (K + 15) >> 4;
    const int nsrc = (A1 != nullptr) ? 2 : 1;
    const int nper = nkt * nsrc;       // tiles per term
    const int ntt  = nper * 3;         // 3 split terms

    float4 va[2], vb[2];
    auto ldregs = [&](int tt) {
        const int rem = tt % nper;
        const int src = rem / nkt, k0 = (rem - src * nkt) * 16;
        const float* Ap = (src ? A1 : A0) + aOff;
        const float* Bp = (src ? B1 : B0) + bOff;
#pragma unroll
        for (int i = 0; i < 2; i++) {
            const int f = t + (i << 8), row = f >> 2, kq = (f & 3) << 2;
            va[i] = ldg4(Ap + (long long)(m0 + row) * lda + k0 + kq,
                         (m0 + row) < M, K - (k0 + kq));
        }
#pragma unroll
        for (int i = 0; i < 2; i++) {
            const int f = t + (i << 8);
            if (f >= BF4) { vb[i] = make_float4(0.f, 0.f, 0.f, 0.f); continue; }
            if (!transB) {
                const int kr = (BN == 128) ? (f >> 5) : (f >> 3);
                const int cq = (BN == 128) ? ((f & 31) << 2) : ((f & 7) << 2);
                vb[i] = ldg4(Bp + (long long)(k0 + kr) * ldb + n0 + cq,
                             (k0 + kr) < K, N - (n0 + cq));
            } else {
                const int nr = f >> 2, kq = (f & 3) << 2;
                vb[i] = ldg4(Bp + (long long)(n0 + nr) * ldb + k0 + kq,
                             (n0 + nr) < N, K - (k0 + kq));
            }
        }
    };
    auto stsmem = [&](int s, int tt) {
        const int term = tt / nper;          // 0: hi*hi, 1: hi*lo, 2: lo*hi
        const bool aLo = (term == 2), bLo = (term == 1);
#pragma unroll
        for (int i = 0; i < 2; i++) {
            const int f = t + (i << 8), row = f >> 2, kq = (f & 3) << 2;
            const float e[4] = {va[i].x, va[i].y, va[i].z, va[i].w};
#pragma unroll
            for (int j = 0; j < 4; j++) sA[s][kq + j][row] = tfterm(e[j], aLo);
        }
#pragma unroll
        for (int i = 0; i < 2; i++) {
            const int f = t + (i << 8);
            if (f >= BF4) continue;
            const float e[4] = {vb[i].x, vb[i].y, vb[i].z, vb[i].w};
#pragma unroll
            for (int j = 0; j < 4; j++) {
                int kk, cc;
                if (!transB) {
                    kk = (BN == 128) ? (f >> 5) : (f >> 3);
                    cc = ((BN == 128) ? ((f & 31) << 2) : ((f & 7) << 2)) + j;
                } else { kk = ((f & 3) << 2) + j; cc = f >> 2; }
                sB[s][kk][cc] = tfterm(e[j], bLo);
            }
        }
    };

    const int rbase = wm * 64 + g, cbase = wn * (BN / 4) + c4 * 2;
    auto compute = [&](int s) {
#pragma unroll
        for (int ks = 0; ks < 2; ks++) {
            const int k8 = ks * 8;
            uint32_t af[4][4], bf[NW][2];
#pragma unroll
            for (int mi = 0; mi < 4; mi++) {
                const int r = rbase + mi * 16;
                af[mi][0] = sA[s][k8 + c4][r];     af[mi][1] = sA[s][k8 + c4][r + 8];
                af[mi][2] = sA[s][k8 + c4 + 4][r]; af[mi][3] = sA[s][k8 + c4 + 4][r + 8];
            }
#pragma unroll
            for (int ni = 0; ni < NW; ni++) {
                const int cc = wn * (BN / 4) + ni * 8 + g;
                bf[ni][0] = sB[s][k8 + c4][cc]; bf[ni][1] = sB[s][k8 + c4 + 4][cc];
            }
#pragma unroll
            for (int mi = 0; mi < 4; mi++)
#pragma unroll
                for (int ni = 0; ni < NW; ni++) mma8(acc[mi][ni], af[mi], bf[ni]);
        }
    };

    ldregs(0); stsmem(0, 0); __syncthreads();
    for (int tt = 0; tt < ntt; tt++) {
        const int cur = tt & 1;
        if (tt + 1 < ntt) ldregs(tt + 1);
        compute(cur);
        __syncthreads();
        if (tt + 1 < ntt) { stsmem(1 - cur, tt + 1); __syncthreads(); }
    }

    // ---- epilogue ----
#pragma unroll
    for (int mi = 0; mi < 4; mi++)
#pragma unroll
        for (int ni = 0; ni < NW; ni++)
#pragma unroll
            for (int j = 0; j < 4; j++) {
                const int row = m0 + rbase + mi * 16 + ((j >> 1) << 3);
                const int col = n0 + cbase + ni * 8 + (j & 1);
                if (row >= M || col >= N) continue;
                float v = acc[mi][ni][j] * alpha;
                if (epMode == 1) v += bias[col];
                else if (epMode == 2) {
                    v = 10.f * tanhf(v);
                    if (col < maskCols) v += Mp[(long long)row * maskCols + col];
                } else if (epMode == 3) {
                    if (col < maskCols) v += Mp[(long long)row * maskCols + col];
                }
                Cp[(long long)row * ldc + col] = v;
            }
}

// ---------------- row softmax (in place, strided rows) -----------------------
__global__ __launch_bounds__(256)
void softmax_kernel(float* __restrict__ X, int rows, int L, int stride)
{
    const int r = (blockIdx.x * blockDim.x + threadIdx.x) >> 5;
    const int lane = threadIdx.x & 31;
    if (r >= rows) return;
    float* rowp = X + (long long)r * stride;
    float vals[7], mx = -INFINITY;
#pragma unroll
    for (int i = 0; i < 7; i++) {
        const int idx = lane + i * 32;
        vals[i] = (idx < L) ? rowp[idx] : -INFINITY;
        mx = fmaxf(mx, vals[i]);
    }
#pragma unroll
    for (int o = 16; o > 0; o >>= 1) mx = fmaxf(mx, __shfl_xor_sync(~0u, mx, o));
    float sum = 0.f;
#pragma unroll
    for (int i = 0; i < 7; i++) {
        const int idx = lane + i * 32;
        vals[i] = (idx < L) ? expf(vals[i] - mx) : 0.f;
        sum += vals[i];
    }
#pragma unroll
    for (int o = 16; o > 0; o >>= 1) sum += __shfl_xor_sync(~0u, sum, o);
    const float inv = 1.f / sum;
#pragma unroll
    for (int i = 0; i < 7; i++) {
        const int idx = lane + i * 32;
        if (idx < L) rowp[idx] = vals[i] * inv;
    }
}

static inline int cdiv(int a, int b) { return (a + b - 1) / b; }

extern "C" void kernel_launch(void* const* d_in, const int* in_sizes, int n_in,
                              void* d_out, int out_size)
{
    const float* nodes = (const float*)d_in[0];
    const float* q1    = (const float*)d_in[1];
    const float* lastn = (const float*)d_in[2];
    const float* ninf  = (const float*)d_in[3];
    const float* Wqf   = (const float*)d_in[4];
    const float* Wql   = (const float*)d_in[5];
    const float* Wk    = (const float*)d_in[6];
    const float* Wv    = (const float*)d_in[7];
    const float* Wc    = (const float*)d_in[8];
    const float* bc    = (const float*)d_in[9];
    float* out = (float*)d_out;

    float *kbuf, *vbuf, *qbuf, *sbuf, *obuf, *mhbuf;
    cudaGetSymbolAddress((void**)&kbuf,  g_kbuf);
    cudaGetSymbolAddress((void**)&vbuf,  g_vbuf);
    cudaGetSymbolAddress((void**)&qbuf,  g_qbuf);
    cudaGetSymbolAddress((void**)&sbuf,  g_sbuf);
    cudaGetSymbolAddress((void**)&obuf,  g_obuf);
    cudaGetSymbolAddress((void**)&mhbuf, g_mhbuf);

    const dim3 blk(256);
    const float isd = 0.17677669529663687f;    // 1/sqrt(32)
    const float ise = 0.04419417382415922f;    // 1/sqrt(512)
    const int Mn = NB * NNODE, Mq = NB * NPOMO;

    // 1) K = nodes @ Wk
    tf32_gemm<128><<<dim3(4, cdiv(Mn, 128), 1), blk>>>(
        nodes, Wk, nullptr, nullptr, nullptr, nullptr, kbuf,
        Mn, NEMB, NEMB, NEMB, NEMB, NEMB, 0,0,0,0,0,0,0, 1, 0, 0, 0, 1.f);
    // 2) V = nodes @ Wv
    tf32_gemm<128><<<dim3(4, cdiv(Mn, 128), 1), blk>>>(
        nodes, Wv, nullptr, nullptr, nullptr, nullptr, vbuf,
        Mn, NEMB, NEMB, NEMB, NEMB, NEMB, 0,0,0,0,0,0,0, 1, 0, 0, 0, 1.f);
    // 3) Q = q1@Wqf + lastn@Wql (dual source)
    tf32_gemm<128><<<dim3(4, cdiv(Mq, 128), 1), blk>>>(
        q1, Wqf, lastn, Wql, nullptr, nullptr, qbuf,
        Mq, NEMB, NEMB, NEMB, NEMB, NEMB, 0,0,0,0,0,0,0, 1, 0, 0, 0, 1.f);
    // 4) S = Q@K^T/sqrt(D) + mask   per (b,h); C stride SLD
    tf32_gemm<128><<<dim3(cdiv(NNODE, 128), cdiv(NPOMO, 128), NB * NHEAD), blk>>>(
        qbuf, kbuf, nullptr, nullptr, nullptr, ninf, sbuf,
        NPOMO, NNODE, NHD, NEMB, NEMB, SLD,
        (long long)NPOMO * NEMB, NHD,
        (long long)NNODE * NEMB, NHD,
        (long long)NHEAD * NPOMO * SLD, (long long)NPOMO * SLD,
        (long long)NPOMO * NPROB,
        NHEAD, 1, 3, NPROB, isd);
    // 5) softmax rows of S
    {
        const int rows = NB * NHEAD * NPOMO;
        softmax_kernel<<<cdiv(rows, 8), blk>>>(sbuf, rows, NNODE, SLD);
    }
    // 6) O = S @ V  per (b,h), interleaved into obuf
    tf32_gemm<32><<<dim3(1, cdiv(NPOMO, 128), NB * NHEAD), blk>>>(
        sbuf, vbuf, nullptr, nullptr, nullptr, nullptr, obuf,
        NPOMO, NHD, NNODE, SLD, NEMB, NEMB,
        (long long)NHEAD * NPOMO * SLD, (long long)NPOMO * SLD,
        (long long)NNODE * NEMB, NHD,
        (long long)NPOMO * NEMB, NHD,
        0, NHEAD, 0, 0, 0, 1.f);
    // 7) mh = O @ Wc + bc
    tf32_gemm<128><<<dim3(4, cdiv(Mq, 128), 1), blk>>>(
        obuf, Wc, nullptr, nullptr, bc, nullptr, mhbuf,
        Mq, NEMB, NEMB, NEMB, NEMB, NEMB, 0,0,0,0,0,0,0, 1, 0, 1, 0, 1.f);
    // 8) out = 10*tanh(mh @ nodes[:,:200]^T / sqrt(EMB)) + ninf
    tf32_gemm<128><<<dim3(cdiv(NPROB, 128), cdiv(NPOMO, 128), NB), blk>>>(
        mhbuf, nodes, nullptr, nullptr, nullptr, ninf, out,
        NPOMO, NPROB, NEMB, NEMB, NEMB, NPROB,
        (long long)NPOMO * NEMB, 0,
        (long long)NNODE * NEMB, 0,
        (long long)NPOMO * NPROB, 0,
        (long long)NPOMO * NPROB,
        1, 1, 2, NPROB, ise);
    // 9) final softmax
    {
        const int rows = NB * NPOMO;
        softmax_kernel<<<cdiv(rows, 8), blk>>>(out, rows, NPROB, NPROB);
    }
}